// round 1
// baseline (speedup 1.0000x reference)
#include <cuda_runtime.h>

// Bidirectional LSTM, H=39, B=512, T=2048, fp32.
// Persistent design: 256 blocks x 160 threads. Each block owns 4 (batch,dir)
// sequences for all T steps (no inter-block dependency -> no global sync).
// Thread t (< 156) owns gate row t: W_ih[t,:] and W_hh[t,:] live in registers.
// x_t and h_{t-1} are broadcast from shared memory; f32x2 packed FMA doubles
// fp32 throughput (ptxas will not auto-fuse; inline PTX required).

#define H        39
#define T_STEPS  2048
#define G4       156          // 4*H
#define SPB      4            // sequences per block
#define THREADS  160
#define KP       20           // padded half-pairs: 40 floats per weight row

union F2U { float2 f; unsigned long long u; };

__device__ __forceinline__ float2 ffma2(float2 a, float2 b, float2 c) {
#if defined(__CUDA_ARCH__) && (__CUDA_ARCH__ >= 1000)
    F2U A, B, C, D;
    A.f = a; B.f = b; C.f = c;
    asm("fma.rn.f32x2 %0, %1, %2, %3;" : "=l"(D.u) : "l"(A.u), "l"(B.u), "l"(C.u));
    return D.f;
#else
    return make_float2(fmaf(a.x, b.x, c.x), fmaf(a.y, b.y, c.y));
#endif
}

__device__ __forceinline__ float fast_tanh(float v) {
    float e = __expf(2.0f * v);
    return __fdividef(e - 1.0f, e + 1.0f);
}

__global__ __launch_bounds__(THREADS) void lstm_bidir_kernel(
    const float* __restrict__ x,
    const float* __restrict__ Wih_f, const float* __restrict__ Whh_f,
    const float* __restrict__ bih_f, const float* __restrict__ bhh_f,
    const float* __restrict__ Wih_b, const float* __restrict__ Whh_b,
    const float* __restrict__ bih_b, const float* __restrict__ bhh_b,
    float* __restrict__ out)
{
    const int tid   = threadIdx.x;
    const int bx    = blockIdx.x;
    const int dir   = bx >> 7;            // 0..127 fwd, 128..255 bwd
    const int bbase = (bx & 127) * SPB;

    const float* Wih = dir ? Wih_b : Wih_f;
    const float* Whh = dir ? Whh_b : Whh_f;
    const float* bih = dir ? bih_b : bih_f;
    const float* bhh = dir ? bhh_b : bhh_f;

    // ---- per-thread weight rows in registers (padded to 40 with zeros) ----
    float2 wih2[KP], whh2[KP];
    float bias = 0.0f;
    const bool grow = (tid < G4);
    #pragma unroll
    for (int k = 0; k < KP; k++) {
        float a0 = 0.f, a1 = 0.f, b0 = 0.f, b1 = 0.f;
        if (grow) {
            const int i0 = 2 * k, i1 = 2 * k + 1;
            a0 = Wih[tid * H + i0];
            b0 = Whh[tid * H + i0];
            if (i1 < H) { a1 = Wih[tid * H + i1]; b1 = Whh[tid * H + i1]; }
        }
        wih2[k] = make_float2(a0, a1);
        whh2[k] = make_float2(b0, b1);
    }
    if (grow) bias = bih[tid] + bhh[tid];
    const int cls = tid / H;   // 0=i, 1=f, 2=g, 3=o (PyTorch gate order)

    // loader / state-update mapping: thread -> (sequence s, hidden index j)
    const int  s   = tid / 40;
    const int  j   = tid - 40 * s;
    const bool upd = (j < H);

    __shared__ __align__(16) float sx [SPB][40];   // x_t per sequence (padded)
    __shared__ __align__(16) float shh[SPB][40];   // h_{t-1} per sequence
    __shared__ float sg[SPB][THREADS];             // gate activations

    for (int idx = tid; idx < SPB * 40; idx += THREADS) {
        (&sx [0][0])[idx] = 0.0f;
        (&shh[0][0])[idx] = 0.0f;
    }

    float c = 0.0f;

    const int bb = bbase + s;
    const float* xp = x + (size_t)bb * (T_STEPS * H) + (dir ? (T_STEPS - 1) * H : 0) + j;
    float*       op = out + (size_t)bb * (T_STEPS * 2 * H) + dir * H + j;
    const int xstep = dir ? -H : H;

    float xcur = 0.0f;
    if (upd) xcur = __ldg(xp);
    const float* xq = xp + xstep;      // prefetch cursor (t+1)

    __syncthreads();

    for (int t = 0; t < T_STEPS; t++) {
        if (upd) sx[s][j] = xcur;
        __syncthreads();               // sx and shh (prev step) visible

        // prefetch x for t+1 while gates compute
        float xnext = 0.0f;
        if (upd && (t + 1 < T_STEPS)) xnext = __ldg(xq);
        xq += xstep;

        // ---- gate pre-activations: one gate row per thread, 4 sequences ----
        #pragma unroll
        for (int ss = 0; ss < SPB; ss++) {
            const float4* x4 = reinterpret_cast<const float4*>(sx[ss]);
            const float4* h4 = reinterpret_cast<const float4*>(shh[ss]);
            float2 aI = make_float2(0.f, 0.f);
            float2 aH = make_float2(0.f, 0.f);
            #pragma unroll
            for (int k = 0; k < 10; k++) {
                const float4 xv = x4[k];
                const float4 hv = h4[k];
                aI = ffma2(wih2[2 * k],     make_float2(xv.x, xv.y), aI);
                aI = ffma2(wih2[2 * k + 1], make_float2(xv.z, xv.w), aI);
                aH = ffma2(whh2[2 * k],     make_float2(hv.x, hv.y), aH);
                aH = ffma2(whh2[2 * k + 1], make_float2(hv.z, hv.w), aH);
            }
            float gv = bias + (aI.x + aI.y) + (aH.x + aH.y);
            // fused activation: sigmoid(v)=1/(1+e^{-v}); tanh(v)=(e^{2v}-1)/(e^{2v}+1)
            const float arg = (cls == 2) ? (gv + gv) : (-gv);
            const float e   = __expf(arg);
            const float num = (cls == 2) ? (e - 1.0f) : 1.0f;
            gv = __fdividef(num, e + 1.0f);
            sg[ss][tid] = gv;
        }
        __syncthreads();               // gates visible

        // ---- c/h update: thread (s,j) owns cell state ----
        if (upd) {
            const float gi = sg[s][j];
            const float gf = sg[s][H + j];
            const float gg = sg[s][2 * H + j];
            const float go = sg[s][3 * H + j];
            c = gf * c + gi * gg;
            const float h = go * fast_tanh(c);
            shh[s][j] = h;
            op[(size_t)t * (2 * H)] = h;
        }
        xcur = xnext;
    }
}

extern "C" void kernel_launch(void* const* d_in, const int* in_sizes, int n_in,
                              void* d_out, int out_size) {
    const float* x     = (const float*)d_in[0];
    const float* Wih_f = (const float*)d_in[1];
    const float* Whh_f = (const float*)d_in[2];
    const float* bih_f = (const float*)d_in[3];
    const float* bhh_f = (const float*)d_in[4];
    const float* Wih_b = (const float*)d_in[5];
    const float* Whh_b = (const float*)d_in[6];
    const float* bih_b = (const float*)d_in[7];
    const float* bhh_b = (const float*)d_in[8];
    float* out = (float*)d_out;

    lstm_bidir_kernel<<<256, THREADS>>>(x, Wih_f, Whh_f, bih_f, bhh_f,
                                        Wih_b, Whh_b, bih_b, bhh_b, out);
}